// round 1
// baseline (speedup 1.0000x reference)
#include <cuda_runtime.h>
#include <cstdint>

#define TASKS  128
#define NSAMP  2048
#define INDIM  256
#define OUTDIM 256
#define XPAD   36   // floats per smem row: 32 samples + 4 pad -> 144B (16B aligned, 4-way STS conflict only)

__device__ __forceinline__ unsigned smem_u32(const void* p) {
    unsigned r;
    asm("{ .reg .u64 t; cvta.to.shared.u64 t, %1; cvt.u32.u64 %0, t; }" : "=r"(r) : "l"(p));
    return r;
}

// Load x tile transposed into smem: x_sm[i][s] for s in [0, scount), zero-padded past cnt.
__device__ __forceinline__ void load_tile(const float* __restrict__ X,
                                          const unsigned short* s_list,
                                          float* x_sm, int base, int cnt, int scount)
{
    const int tid = threadIdx.x;
    #pragma unroll 1
    for (int ii = tid; ii < INDIM; ii += 128) {
        #pragma unroll 1
        for (int s = 0; s < scount; ++s) {
            const int idx = base + s;
            float v = 0.0f;
            if (idx < cnt) v = X[(unsigned)s_list[idx] * INDIM + ii];
            x_sm[ii * XPAD + s] = v;
        }
    }
}

template<int PAIRS>
__device__ __forceinline__ void compute_store(
    const float* __restrict__ Wt, float* __restrict__ OUT,
    const unsigned short* s_list, unsigned xb, int base, int cnt, int o)
{
    unsigned long long acc[PAIRS];
    #pragma unroll
    for (int k = 0; k < PAIRS; ++k) acc[k] = 0ull;

    #pragma unroll 1
    for (int i0 = 0; i0 < INDIM; i0 += 16) {
        // Batch 16 independent W loads for MLP (L2-latency hiding).
        float wv[16];
        #pragma unroll
        for (int j = 0; j < 16; ++j)
            wv[j] = __ldg(Wt + (size_t)(i0 + j) * OUTDIM);

        #pragma unroll
        for (int j = 0; j < 16; ++j) {
            unsigned long long wd;
            {
                unsigned wu = __float_as_uint(wv[j]);
                asm("mov.b64 %0, {%1, %1};" : "=l"(wd) : "r"(wu));
            }
            const unsigned addr = xb + (unsigned)(i0 + j) * (XPAD * 4);
            if (PAIRS == 1) {
                unsigned long long a;
                asm("ld.shared.b64 %0, [%1];" : "=l"(a) : "r"(addr));
                asm("fma.rn.f32x2 %0, %1, %2, %0;" : "+l"(acc[0]) : "l"(a), "l"(wd));
            } else {
                #pragma unroll
                for (int k2 = 0; k2 < PAIRS / 2; ++k2) {
                    unsigned long long a, b;
                    asm("ld.shared.v2.b64 {%0, %1}, [%2];"
                        : "=l"(a), "=l"(b) : "r"(addr + (unsigned)k2 * 16));
                    asm("fma.rn.f32x2 %0, %1, %2, %0;" : "+l"(acc[2 * k2])     : "l"(a), "l"(wd));
                    asm("fma.rn.f32x2 %0, %1, %2, %0;" : "+l"(acc[2 * k2 + 1]) : "l"(b), "l"(wd));
                }
            }
        }
    }

    #pragma unroll
    for (int k = 0; k < PAIRS; ++k) {
        unsigned lo, hi;
        asm("mov.b64 {%0, %1}, %2;" : "=r"(lo), "=r"(hi) : "l"(acc[k]));
        const int s0 = base + 2 * k, s1 = s0 + 1;
        if (s0 < cnt) OUT[(unsigned)s_list[s0] * OUTDIM + o] = __uint_as_float(lo);
        if (s1 < cnt) OUT[(unsigned)s_list[s1] * OUTDIM + o] = __uint_as_float(hi);
    }
}

__global__ __launch_bounds__(128)
void tsl_kernel(const float* __restrict__ X,
                const void*  __restrict__ TIDS,
                const float* __restrict__ W,
                float* __restrict__ OUT)
{
    __shared__ __align__(16) float x_sm[INDIM * XPAD];
    __shared__ unsigned short s_list[NSAMP];
    __shared__ int s_cnt;
    __shared__ unsigned s_or;

    const int tid  = threadIdx.x;
    const int task = blockIdx.x & (TASKS - 1);
    const int half = blockIdx.x >> 7;
    const int o    = half * 128 + tid;

    if (tid == 0) { s_cnt = 0; s_or = 0; }
    __syncthreads();

    // Detect task_ids dtype: int64 (odd 32-bit words all zero) vs int32.
    {
        const unsigned* w32 = (const unsigned*)TIDS;
        unsigned v = 0;
        for (int j = tid; j < 256; j += 128) v |= w32[2 * j + 1];
        atomicOr(&s_or, v);
    }
    __syncthreads();
    const bool is64 = (s_or == 0);

    // Build this task's sample list.
    if (is64) {
        const long long* t64 = (const long long*)TIDS;
        for (int n = tid; n < NSAMP; n += 128)
            if ((int)t64[n] == task) {
                int p = atomicAdd(&s_cnt, 1);
                s_list[p] = (unsigned short)n;
            }
    } else {
        const int* t32 = (const int*)TIDS;
        for (int n = tid; n < NSAMP; n += 128)
            if (t32[n] == task) {
                int p = atomicAdd(&s_cnt, 1);
                s_list[p] = (unsigned short)n;
            }
    }
    __syncthreads();
    const int cnt = s_cnt;
    if (cnt == 0) return;

    const float* Wt = W + (size_t)task * INDIM * OUTDIM + o;
    const unsigned xb = smem_u32(x_sm);

    int base = 0;
    while (cnt - base >= 32) {
        load_tile(X, s_list, x_sm, base, cnt, 32);
        __syncthreads();
        compute_store<16>(Wt, OUT, s_list, xb, base, cnt, o);
        base += 32;
        __syncthreads();
    }

    const int rem = cnt - base;
    if (rem > 0) {
        const int P = (rem > 16) ? 16 : (rem > 8) ? 8 : (rem > 4) ? 4 : (rem > 2) ? 2 : 1;
        load_tile(X, s_list, x_sm, base, cnt, 2 * P);
        __syncthreads();
        switch (P) {
            case 16: compute_store<16>(Wt, OUT, s_list, xb, base, cnt, o); break;
            case 8:  compute_store<8 >(Wt, OUT, s_list, xb, base, cnt, o); break;
            case 4:  compute_store<4 >(Wt, OUT, s_list, xb, base, cnt, o); break;
            case 2:  compute_store<2 >(Wt, OUT, s_list, xb, base, cnt, o); break;
            default: compute_store<1 >(Wt, OUT, s_list, xb, base, cnt, o); break;
        }
    }
}

extern "C" void kernel_launch(void* const* d_in, const int* in_sizes, int n_in,
                              void* d_out, int out_size)
{
    const float* X    = (const float*)d_in[0];
    const void*  TIDS = d_in[1];
    const float* W    = (const float*)d_in[2];
    float*       OUT  = (float*)d_out;
    tsl_kernel<<<256, 128>>>(X, TIDS, W, OUT);
}

// round 2
// speedup vs baseline: 1.1302x; 1.1302x over previous
#include <cuda_runtime.h>
#include <cstdint>

#define TASKS  128
#define NSAMP  2048
#define INDIM  256
#define OUTDIM 256
#define XPAD   36   // floats per smem row: 32 samples + 4 pad; rows 144B (16B aligned)

__device__ __forceinline__ unsigned smem_u32(const void* p) {
    unsigned r;
    asm("{ .reg .u64 t; cvta.to.shared.u64 t, %1; cvt.u32.u64 %0, t; }" : "=r"(r) : "l"(p));
    return r;
}

// Conflict-free transposed tile load: x_sm[i][s], s in [0,scount), zero-pad past cnt.
// thread t -> s = t&31, iv-quarter = t>>5. For fixed iv, lanes write consecutive banks.
__device__ __forceinline__ void load_tile(const float* __restrict__ X,
                                          const unsigned short* s_list,
                                          float* x_sm, int base, int cnt, int scount)
{
    const int t  = threadIdx.x;
    const int s  = t & 31;
    const int q  = t >> 5;           // 0..3
    if (s >= scount) return;         // columns never read this tile
    const int idx = base + s;
    const bool valid = (idx < cnt);
    const float4* row = (const float4*)(X + (valid ? (unsigned)s_list[idx] * INDIM : 0u));
    #pragma unroll
    for (int iv = q; iv < 64; iv += 4) {
        float4 v;
        if (valid) v = __ldg(row + iv);
        else       v = make_float4(0.f, 0.f, 0.f, 0.f);
        const int i = iv * 4;
        x_sm[(i + 0) * XPAD + s] = v.x;
        x_sm[(i + 1) * XPAD + s] = v.y;
        x_sm[(i + 2) * XPAD + s] = v.z;
        x_sm[(i + 3) * XPAD + s] = v.w;
    }
}

template<int PAIRS>
__device__ __forceinline__ void compute_store(
    const float* __restrict__ Wt, float* __restrict__ OUT,
    const unsigned short* s_list, unsigned xb, int base, int cnt, int o)
{
    unsigned long long acc[PAIRS];
    #pragma unroll
    for (int k = 0; k < PAIRS; ++k) acc[k] = 0ull;

    float w0[8], w1[8];
    #pragma unroll
    for (int j = 0; j < 8; ++j) w0[j] = __ldg(Wt + (size_t)j * OUTDIM);

    #pragma unroll 2
    for (int b = 0; b < 32; ++b) {               // 32 batches of 8 i-values
        float* cur = (b & 1) ? w1 : w0;
        float* nxt = (b & 1) ? w0 : w1;
        if (b < 31) {                            // prefetch next batch (hides L2 latency)
            #pragma unroll
            for (int j = 0; j < 8; ++j)
                nxt[j] = __ldg(Wt + (size_t)((b + 1) * 8 + j) * OUTDIM);
        }
        #pragma unroll
        for (int j = 0; j < 8; ++j) {
            unsigned long long wd;
            {
                unsigned wu = __float_as_uint(cur[j]);
                asm("mov.b64 %0, {%1, %1};" : "=l"(wd) : "r"(wu));
            }
            const unsigned addr = xb + (unsigned)(b * 8 + j) * (XPAD * 4);
            if (PAIRS == 1) {
                unsigned long long a;
                asm("ld.shared.b64 %0, [%1];" : "=l"(a) : "r"(addr));
                asm("fma.rn.f32x2 %0, %1, %2, %0;" : "+l"(acc[0]) : "l"(a), "l"(wd));
            } else {
                #pragma unroll
                for (int k2 = 0; k2 < PAIRS / 2; ++k2) {
                    unsigned long long a, b2;
                    asm("ld.shared.v2.b64 {%0, %1}, [%2];"
                        : "=l"(a), "=l"(b2) : "r"(addr + (unsigned)k2 * 16));
                    asm("fma.rn.f32x2 %0, %1, %2, %0;" : "+l"(acc[2 * k2])     : "l"(a),  "l"(wd));
                    asm("fma.rn.f32x2 %0, %1, %2, %0;" : "+l"(acc[2 * k2 + 1]) : "l"(b2), "l"(wd));
                }
            }
        }
    }

    #pragma unroll
    for (int k = 0; k < PAIRS; ++k) {
        unsigned lo, hi;
        asm("mov.b64 {%0, %1}, %2;" : "=r"(lo), "=r"(hi) : "l"(acc[k]));
        const int s0 = base + 2 * k, s1 = s0 + 1;
        if (s0 < cnt) OUT[(unsigned)s_list[s0] * OUTDIM + o] = __uint_as_float(lo);
        if (s1 < cnt) OUT[(unsigned)s_list[s1] * OUTDIM + o] = __uint_as_float(hi);
    }
}

__global__ __launch_bounds__(128)
void tsl_kernel(const float* __restrict__ X,
                const void*  __restrict__ TIDS,
                const float* __restrict__ W,
                float* __restrict__ OUT)
{
    __shared__ __align__(16) float x_sm[INDIM * XPAD];
    __shared__ unsigned short s_list[NSAMP];
    __shared__ int s_cnt;
    __shared__ unsigned s_or;

    const int tid  = threadIdx.x;
    const int lane = tid & 31;
    const int task = blockIdx.x & (TASKS - 1);
    const int half = blockIdx.x >> 7;
    const int o    = half * 128 + tid;

    if (tid == 0) { s_cnt = 0; s_or = 0; }
    __syncthreads();

    const unsigned* w32 = (const unsigned*)TIDS;

    // dtype detect: int64 iff all odd 32-bit words (high halves) are zero.
    {
        unsigned v = w32[2 * tid + 1] | w32[2 * (tid + 128) + 1]
                   | w32[2 * (tid + 256) + 1] | w32[2 * (tid + 384) + 1];
        atomicOr(&s_or, v);
    }
    __syncthreads();
    const int shift = (s_or == 0) ? 1 : 0;

    // Ballot-compress scan: all 16 id loads issued up-front (full MLP).
    {
        unsigned w[16];
        #pragma unroll
        for (int r = 0; r < 16; ++r)
            w[r] = w32[(unsigned)(r * 128 + tid) << shift];
        #pragma unroll
        for (int r = 0; r < 16; ++r) {
            const bool m = (w[r] == (unsigned)task);
            const unsigned bal = __ballot_sync(0xffffffffu, m);
            if (bal) {
                int wbase = 0;
                if (lane == 0) wbase = atomicAdd(&s_cnt, __popc(bal));
                wbase = __shfl_sync(0xffffffffu, wbase, 0);
                if (m) s_list[wbase + __popc(bal & ((1u << lane) - 1u))]
                           = (unsigned short)(r * 128 + tid);
            }
        }
    }
    __syncthreads();
    const int cnt = s_cnt;
    if (cnt == 0) return;

    const float* Wt = W + (size_t)task * INDIM * OUTDIM + o;
    const unsigned xb = smem_u32(x_sm);

    int base = 0;
    while (cnt - base >= 32) {
        load_tile(X, s_list, x_sm, base, cnt, 32);
        __syncthreads();
        compute_store<16>(Wt, OUT, s_list, xb, base, cnt, o);
        base += 32;
        __syncthreads();
    }

    const int rem = cnt - base;
    if (rem > 0) {
        const int P = (rem > 16) ? 16 : (rem > 8) ? 8 : (rem > 4) ? 4 : (rem > 2) ? 2 : 1;
        load_tile(X, s_list, x_sm, base, cnt, 2 * P);
        __syncthreads();
        switch (P) {
            case 16: compute_store<16>(Wt, OUT, s_list, xb, base, cnt, o); break;
            case 8:  compute_store<8 >(Wt, OUT, s_list, xb, base, cnt, o); break;
            case 4:  compute_store<4 >(Wt, OUT, s_list, xb, base, cnt, o); break;
            case 2:  compute_store<2 >(Wt, OUT, s_list, xb, base, cnt, o); break;
            default: compute_store<1 >(Wt, OUT, s_list, xb, base, cnt, o); break;
        }
    }
}

extern "C" void kernel_launch(void* const* d_in, const int* in_sizes, int n_in,
                              void* d_out, int out_size)
{
    const float* X    = (const float*)d_in[0];
    const void*  TIDS = d_in[1];
    const float* W    = (const float*)d_in[2];
    float*       OUT  = (float*)d_out;
    tsl_kernel<<<256, 128>>>(X, TIDS, W, OUT);
}

// round 3
// speedup vs baseline: 1.3101x; 1.1592x over previous
#include <cuda_runtime.h>
#include <cstdint>

#define TASKS  128
#define NSAMP  2048
#define INDIM  256
#define OUTDIM 256
#define TILE   16
#define XPAD   20      // 16 samples + 4 pad; row = 80B (16B-aligned)
#define MAXGRID 512    // 2 halves * max 256 work units

__device__ unsigned short g_slist[NSAMP];
__device__ int g_soff[TASKS + 1];
__device__ int g_twoff[TASKS + 1];

__device__ __forceinline__ unsigned smem_u32(const void* p) {
    unsigned r;
    asm("{ .reg .u64 t; cvta.to.shared.u64 t, %1; cvt.u32.u64 %0, t; }" : "=r"(r) : "l"(p));
    return r;
}

// ---------------- K1: build per-task sample lists + tile worklist prefix ----------------
__global__ __launch_bounds__(256) void k1_scan(const void* __restrict__ TIDS)
{
    __shared__ int cnts[TASKS];
    __shared__ int cursor[TASKS];
    __shared__ int soff[TASKS + 1];
    __shared__ int twoff[TASKS + 1];
    __shared__ int scan_tmp[TASKS];
    __shared__ unsigned orv;

    const int tid = threadIdx.x;
    if (tid < TASKS) { cnts[tid] = 0; cursor[tid] = 0; }
    if (tid == 0) orv = 0;
    __syncthreads();

    const unsigned* w32 = (const unsigned*)TIDS;
    // dtype detect: int64 iff high 32-bit words are all zero (check first 512 samples).
    atomicOr(&orv, w32[4 * tid + 1] | w32[4 * tid + 3]);
    __syncthreads();
    const int shift = (orv == 0) ? 1 : 0;

    int myid[8];
    #pragma unroll
    for (int j = 0; j < 8; ++j) {
        const int n = tid + 256 * j;
        myid[j] = (int)w32[(unsigned)n << shift];
        atomicAdd(&cnts[myid[j]], 1);
    }
    __syncthreads();

    // inclusive scan of cnts -> soff (exclusive form)
    if (tid < TASKS) scan_tmp[tid] = cnts[tid];
    __syncthreads();
    #pragma unroll
    for (int d = 1; d < TASKS; d <<= 1) {
        int v = 0;
        if (tid < TASKS && tid >= d) v = scan_tmp[tid - d];
        __syncthreads();
        if (tid < TASKS) scan_tmp[tid] += v;
        __syncthreads();
    }
    if (tid < TASKS) soff[tid + 1] = scan_tmp[tid];
    if (tid == 0) soff[0] = 0;
    __syncthreads();

    // inclusive scan of ceil(cnt/TILE) -> twoff
    if (tid < TASKS) scan_tmp[tid] = (cnts[tid] + TILE - 1) / TILE;
    __syncthreads();
    #pragma unroll
    for (int d = 1; d < TASKS; d <<= 1) {
        int v = 0;
        if (tid < TASKS && tid >= d) v = scan_tmp[tid - d];
        __syncthreads();
        if (tid < TASKS) scan_tmp[tid] += v;
        __syncthreads();
    }
    if (tid < TASKS) twoff[tid + 1] = scan_tmp[tid];
    if (tid == 0) twoff[0] = 0;
    __syncthreads();

    // scatter sample indices (order within a task is irrelevant: each sample's
    // own i-reduction order is fixed, so outputs are bitwise deterministic)
    #pragma unroll
    for (int j = 0; j < 8; ++j) {
        const int n = tid + 256 * j;
        const int t = myid[j];
        const int p = atomicAdd(&cursor[t], 1);
        g_slist[soff[t] + p] = (unsigned short)n;
    }
    if (tid <= TASKS) { g_soff[tid] = soff[tid]; g_twoff[tid] = twoff[tid]; }
}

// ---------------- K2: one CTA = one (16-sample tile, 128-col half) ----------------
template<int PAIRS>
__device__ __forceinline__ void compute_store(
    const float* __restrict__ Wt, float* __restrict__ OUT,
    const unsigned short* sl, unsigned xb, int scount, int o)
{
    unsigned long long acc[PAIRS];
    #pragma unroll
    for (int k = 0; k < PAIRS; ++k) acc[k] = 0ull;

    float w0[8], w1[8];
    #pragma unroll
    for (int j = 0; j < 8; ++j) w0[j] = __ldg(Wt + (size_t)j * OUTDIM);

    #pragma unroll 2
    for (int b = 0; b < 32; ++b) {
        float* cur = (b & 1) ? w1 : w0;
        float* nxt = (b & 1) ? w0 : w1;
        if (b < 31) {
            #pragma unroll
            for (int j = 0; j < 8; ++j)
                nxt[j] = __ldg(Wt + (size_t)((b + 1) * 8 + j) * OUTDIM);
        }
        #pragma unroll
        for (int j = 0; j < 8; ++j) {
            unsigned long long wd;
            {
                unsigned wu = __float_as_uint(cur[j]);
                asm("mov.b64 %0, {%1, %1};" : "=l"(wd) : "r"(wu));
            }
            const unsigned addr = xb + (unsigned)(b * 8 + j) * (XPAD * 4);
            if (PAIRS == 1) {
                unsigned long long a;
                asm("ld.shared.b64 %0, [%1];" : "=l"(a) : "r"(addr));
                asm("fma.rn.f32x2 %0, %1, %2, %0;" : "+l"(acc[0]) : "l"(a), "l"(wd));
            } else {
                #pragma unroll
                for (int k2 = 0; k2 < PAIRS / 2; ++k2) {
                    unsigned long long a, b2;
                    asm("ld.shared.v2.b64 {%0, %1}, [%2];"
                        : "=l"(a), "=l"(b2) : "r"(addr + (unsigned)k2 * 16));
                    asm("fma.rn.f32x2 %0, %1, %2, %0;" : "+l"(acc[2 * k2])     : "l"(a),  "l"(wd));
                    asm("fma.rn.f32x2 %0, %1, %2, %0;" : "+l"(acc[2 * k2 + 1]) : "l"(b2), "l"(wd));
                }
            }
        }
    }

    #pragma unroll
    for (int k = 0; k < PAIRS; ++k) {
        unsigned lo, hi;
        asm("mov.b64 {%0, %1}, %2;" : "=r"(lo), "=r"(hi) : "l"(acc[k]));
        const int s0 = 2 * k, s1 = s0 + 1;
        if (s0 < scount) OUT[(unsigned)sl[s0] * OUTDIM + o] = __uint_as_float(lo);
        if (s1 < scount) OUT[(unsigned)sl[s1] * OUTDIM + o] = __uint_as_float(hi);
    }
}

__global__ __launch_bounds__(128)
void k2_gemm(const float* __restrict__ X,
             const float* __restrict__ W,
             float* __restrict__ OUT)
{
    __shared__ __align__(16) float x_sm[INDIM * XPAD];
    __shared__ unsigned short sl[TILE];
    __shared__ int s_task, s_base, s_cnt;

    const int tid  = threadIdx.x;
    const int w    = blockIdx.x >> 1;
    const int half = blockIdx.x & 1;

    if (w >= g_twoff[TASKS]) return;

    if (tid < TASKS) {
        const int lo = g_twoff[tid], hi = g_twoff[tid + 1];
        if (lo <= w && w < hi) {
            const int so   = g_soff[tid];
            const int cntt = g_soff[tid + 1] - so;
            const int tile = w - lo;
            s_task = tid;
            s_base = so + tile * TILE;
            int sc = cntt - tile * TILE;
            s_cnt  = (sc > TILE) ? TILE : sc;
        }
    }
    __syncthreads();
    const int task = s_task, base = s_base, scount = s_cnt;

    if (tid < TILE) sl[tid] = (tid < scount) ? g_slist[base + tid] : (unsigned short)0;
    __syncthreads();

    // transposed tile load: thread -> (s = tid&15, q = tid>>4), 8 float4 rows each
    {
        const int s = tid & 15, q = tid >> 4;
        const bool valid = (s < scount);
        const float4* row = (const float4*)(X + (valid ? (unsigned)sl[s] * INDIM : 0u));
        #pragma unroll
        for (int k = 0; k < 8; ++k) {
            const int iv = q + 8 * k;
            float4 v;
            if (valid) v = __ldg(row + iv);
            else       v = make_float4(0.f, 0.f, 0.f, 0.f);
            const int i = iv * 4;
            x_sm[(i + 0) * XPAD + s] = v.x;
            x_sm[(i + 1) * XPAD + s] = v.y;
            x_sm[(i + 2) * XPAD + s] = v.z;
            x_sm[(i + 3) * XPAD + s] = v.w;
        }
    }
    __syncthreads();

    const int o = half * 128 + tid;
    const float* Wt = W + (size_t)task * INDIM * OUTDIM + o;
    const unsigned xb = smem_u32(x_sm);

    const int P = (scount > 8) ? 8 : (scount > 4) ? 4 : (scount > 2) ? 2 : 1;
    switch (P) {
        case 8:  compute_store<8>(Wt, OUT, sl, xb, scount, o); break;
        case 4:  compute_store<4>(Wt, OUT, sl, xb, scount, o); break;
        case 2:  compute_store<2>(Wt, OUT, sl, xb, scount, o); break;
        default: compute_store<1>(Wt, OUT, sl, xb, scount, o); break;
    }
}

extern "C" void kernel_launch(void* const* d_in, const int* in_sizes, int n_in,
                              void* d_out, int out_size)
{
    const float* X    = (const float*)d_in[0];
    const void*  TIDS = d_in[1];
    const float* W    = (const float*)d_in[2];
    float*       OUT  = (float*)d_out;

    k1_scan<<<1, 256>>>(TIDS);
    k2_gemm<<<MAXGRID, 128>>>(X, W, OUT);
}